// round 8
// baseline (speedup 1.0000x reference)
#include <cuda_runtime.h>

#define FULLMASK 0xFFFFFFFFu

namespace {
constexpr int N_SEQ = 4096;
constexpr int T = 128;
constexpr int NCHUNK = 8;
constexpr int CH_SEQ = N_SEQ / NCHUNK;        // 512 sequences per chunk
constexpr int CH_ITEMS = CH_SEQ * T;          // 65536 items per chunk
constexpr float NEG_HALF_LOG2PI = -0.91893853320467274f;
}

__device__ float g_enc[(size_t)N_SEQ * T * 8];
__device__ float g_th[(size_t)N_SEQ * T * 32];
__device__ float g_logp[(size_t)N_SEQ * T];
__device__ float g_dummy[32];

typedef unsigned long long u64;

__device__ __forceinline__ u64 pack2(float lo, float hi)
{
    u64 r;
    asm("mov.b64 %0, {%1, %2};" : "=l"(r) : "f"(lo), "f"(hi));
    return r;
}
__device__ __forceinline__ void unpack2(u64 v, float& lo, float& hi)
{
    asm("mov.b64 {%0, %1}, %2;" : "=f"(lo), "=f"(hi) : "l"(v));
}
__device__ __forceinline__ u64 fma2(u64 a, u64 b, u64 c)
{
    u64 d;
    asm("fma.rn.f32x2 %0, %1, %2, %3;" : "=l"(d) : "l"(a), "l"(b), "l"(c));
    return d;
}
__device__ __forceinline__ u64 mul2(u64 a, u64 b)
{
    u64 d;
    asm("mul.rn.f32x2 %0, %1, %2;" : "=l"(d) : "l"(a), "l"(b));
    return d;
}

// ---------------- probes (2x, so the ncu 4th-launch window = rec chunk 0)
__global__ void probe_kernel()
{
    if (threadIdx.x == 0 && blockIdx.x == 0) g_dummy[0] = 1.0f;
}
__global__ void probe2_kernel()
{
    if (threadIdx.x == 0 && blockIdx.x == 0) g_dummy[1] = 1.0f;
}

// ---------------- encoder: g_enc[n][t][d] = tanh(relu(x*w1+b1) @ w2 + b2)
__global__ void enc_kernel(const float* __restrict__ x,
                           const float* __restrict__ e1w, const float* __restrict__ e1b,
                           const float* __restrict__ e2w, const float* __restrict__ e2b)
{
    __shared__ float s1w[64], s1b[64], s2w[64 * 8], s2b[8];
    int tid = threadIdx.x;
    if (tid < 64) { s1w[tid] = e1w[tid]; s1b[tid] = e1b[tid]; }
    if (tid < 8) s2b[tid] = e2b[tid];
    for (int i = tid; i < 64 * 8; i += blockDim.x) s2w[i] = e2w[i];
    __syncthreads();
    int idx = blockIdx.x * blockDim.x + tid;
    if (idx >= N_SEQ * T) return;
    float xv = x[idx];
    float acc[8];
#pragma unroll
    for (int d = 0; d < 8; d++) acc[d] = s2b[d];
#pragma unroll 8
    for (int h = 0; h < 64; h++) {
        float e = fmaxf(fmaf(xv, s1w[h], s1b[h]), 0.f);
#pragma unroll
        for (int d = 0; d < 8; d++) acc[d] = fmaf(e, s2w[h * 8 + d], acc[d]);
    }
    float4 o0 = make_float4(tanhf(acc[0]), tanhf(acc[1]), tanhf(acc[2]), tanhf(acc[3]));
    float4 o1 = make_float4(tanhf(acc[4]), tanhf(acc[5]), tanhf(acc[6]), tanhf(acc[7]));
    float4* op = reinterpret_cast<float4*>(g_enc + (size_t)idx * 8);
    op[0] = o0;
    op[1] = o1;
}

// ---------------- recurrence (R6/R3 design, chunked): 2-warp pair, 4 seqs,
// i-contraction split across the pair, shuffle broadcast, one named 64-thread
// barrier per step, parity double-buffered partials, e prefetched.
// Block = 128 threads = 2 pairs = 8 sequences. Grid = CH_SEQ/8 = 64 per chunk.
__global__ void __launch_bounds__(128) rec_kernel(const float* __restrict__ A,
                                                  const float* __restrict__ initw,
                                                  int n_base)
{
    __shared__ ulonglong2 A4[2048];      // [(i*2+q)*32 + L]
    __shared__ float part[2][4][4][32];  // [parity][warpInBlock][seq][lane]
    __shared__ float in_s[32];

    int tid = threadIdx.x;
    for (int idx = tid; idx < 2048; idx += 128) {
        int i = idx >> 6, q = (idx >> 5) & 1, L = idx & 31;
        const float* base = A + i * 256 + q * 128 + L;
        ulonglong2 v;
        v.x = pack2(base[0], base[32]);
        v.y = pack2(base[64], base[96]);
        A4[idx] = v;
    }
    if (tid < 32) in_s[tid] = initw[tid];
    __syncthreads();

    int wib = tid >> 5;          // 0..3 warp in block
    int pairIB = wib >> 1;       // 0..1
    int half = wib & 1;          // which i half
    int L = tid & 31;
    int pairG = blockIdx.x * 2 + pairIB;
    int n0 = n_base + pairG * 4;
    int barId = 1 + pairIB;

    float tmp[4];
    float init = in_s[L];
#pragma unroll
    for (int s = 0; s < 4; s++) tmp[s] = init;

    {
        float th0 = tanhf(init);
        int s0 = half * 2;
        g_th[((size_t)(n0 + s0) * T) * 32 + L] = th0;
        g_th[((size_t)(n0 + s0 + 1) * T) * 32 + L] = th0;
    }

    const float4* ep[4];
#pragma unroll
    for (int s = 0; s < 4; s++)
        ep[s] = reinterpret_cast<const float4*>(g_enc + (size_t)(n0 + s) * T * 8);

    int iBase = half * 16;

    float4 ec0[4], ec1[4];
#pragma unroll
    for (int s = 0; s < 4; s++) { ec0[s] = ep[s][0]; ec1[s] = ep[s][1]; }

#pragma unroll 1
    for (int t = 1; t < T; t++) {
        int tn = (t < T - 1) ? t : T - 2;
        float4 en0[4], en1[4];
#pragma unroll
        for (int s = 0; s < 4; s++) { en0[s] = ep[s][tn * 2]; en1[s] = ep[s][tn * 2 + 1]; }

        u64 B[4][4];
#pragma unroll
        for (int s = 0; s < 4; s++)
#pragma unroll
            for (int k = 0; k < 4; k++) B[s][k] = 0ull;

#pragma unroll 8
        for (int ii = 0; ii < 16; ii++) {
            int i = iBase + ii;
            ulonglong2 a0 = A4[(i * 2 + 0) * 32 + L];
            ulonglong2 a1 = A4[(i * 2 + 1) * 32 + L];
#pragma unroll
            for (int s = 0; s < 4; s++) {
                float vs = __shfl_sync(FULLMASK, tmp[s], i);
                u64 vv = pack2(vs, vs);
                B[s][0] = fma2(vv, a0.x, B[s][0]);
                B[s][1] = fma2(vv, a0.y, B[s][1]);
                B[s][2] = fma2(vv, a1.x, B[s][2]);
                B[s][3] = fma2(vv, a1.y, B[s][3]);
            }
        }

        int par = t & 1;
#pragma unroll
        for (int s = 0; s < 4; s++) {
            u64 acc = mul2(pack2(ec0[s].x, ec0[s].y), B[s][0]);
            acc = fma2(pack2(ec0[s].z, ec0[s].w), B[s][1], acc);
            acc = fma2(pack2(ec1[s].x, ec1[s].y), B[s][2], acc);
            acc = fma2(pack2(ec1[s].z, ec1[s].w), B[s][3], acc);
            float lo, hi;
            unpack2(acc, lo, hi);
            part[par][wib][s][L] = lo + hi;
        }

        asm volatile("bar.sync %0, 64;" :: "r"(barId) : "memory");

        int partner = wib ^ 1;
#pragma unroll
        for (int s = 0; s < 4; s++)
            tmp[s] = part[par][wib][s][L] + part[par][partner][s][L];

        int s0 = half * 2;
        g_th[((size_t)(n0 + s0) * T + t) * 32 + L] = tanhf(tmp[s0]);
        g_th[((size_t)(n0 + s0 + 1) * T + t) * 32 + L] = tanhf(tmp[s0 + 1]);

#pragma unroll
        for (int s = 0; s < 4; s++) { ec0[s] = en0[s]; ec1[s] = en1[s]; }
    }
}

// ---------------- phi (R7 design, chunked): two items per thread.
__global__ void __launch_bounds__(128) phi_kernel(
    const float* __restrict__ x,
    const float* __restrict__ w1, const float* __restrict__ b1,
    const float* __restrict__ w2, const float* __restrict__ b2,
    const float* __restrict__ muw, const float* __restrict__ mub,
    const float* __restrict__ sgw, const float* __restrict__ sgb,
    const float* __restrict__ alw, const float* __restrict__ alb,
    int item_base)
{
    __shared__ float sm[8352];
    int tid = threadIdx.x;

    for (int i = tid; i < 2048; i += 128) sm[i] = w1[i];
    for (int i = tid; i < 4096; i += 128) sm[2048 + i] = w2[i];
    for (int i = tid; i < 2048; i += 128) {
        int k = i >> 5, c = i & 31;
        float v = 0.f;
        if (c < 10) v = muw[k * 10 + c];
        else if (c < 20) v = sgw[k * 10 + (c - 10)];
        else if (c < 30) v = alw[k * 10 + (c - 20)];
        sm[6144 + i] = v;
    }
    if (tid < 64) { sm[8192 + tid] = b1[tid]; sm[8256 + tid] = b2[tid]; }
    if (tid < 32) {
        float v = 0.f;
        if (tid < 10) v = mub[tid];
        else if (tid < 20) v = sgb[tid - 10];
        else if (tid < 30) v = alb[tid - 20];
        sm[8320 + tid] = v;
    }
    __syncthreads();

    const ulonglong2* w1v = reinterpret_cast<const ulonglong2*>(sm);
    const ulonglong2* w2v = reinterpret_cast<const ulonglong2*>(sm + 2048);
    const ulonglong2* whv = reinterpret_cast<const ulonglong2*>(sm + 6144);
    const u64* b1u = reinterpret_cast<const u64*>(sm + 8192);
    const u64* b2u = reinterpret_cast<const u64*>(sm + 8256);
    const u64* hbu = reinterpret_cast<const u64*>(sm + 8320);

    int ia = item_base + blockIdx.x * 128 + tid;
    int ib = ia + CH_ITEMS / 2;
    const float4* tpa = reinterpret_cast<const float4*>(g_th + (size_t)ia * 32);
    const float4* tpb = reinterpret_cast<const float4*>(g_th + (size_t)ib * 32);

    float tha[32], thb[32];
#pragma unroll
    for (int g = 0; g < 8; g++) {
        float4 v = tpa[g];
        tha[4 * g] = v.x; tha[4 * g + 1] = v.y; tha[4 * g + 2] = v.z; tha[4 * g + 3] = v.w;
        float4 u = tpb[g];
        thb[4 * g] = u.x; thb[4 * g + 1] = u.y; thb[4 * g + 2] = u.z; thb[4 * g + 3] = u.w;
    }

    // ---- layer 1: 2 chunks of 32 neurons
    float h1a[64], h1b[64];
#pragma unroll
    for (int c = 0; c < 2; c++) {
        u64 A0[16], A1[16];
#pragma unroll
        for (int p = 0; p < 16; p++) { A0[p] = b1u[c * 16 + p]; A1[p] = A0[p]; }
#pragma unroll
        for (int i = 0; i < 32; i++) {
            u64 va = pack2(tha[i], tha[i]);
            u64 vb = pack2(thb[i], thb[i]);
#pragma unroll
            for (int q = 0; q < 8; q++) {
                ulonglong2 w = w1v[i * 16 + c * 8 + q];
                A0[2 * q]     = fma2(va, w.x, A0[2 * q]);
                A0[2 * q + 1] = fma2(va, w.y, A0[2 * q + 1]);
                A1[2 * q]     = fma2(vb, w.x, A1[2 * q]);
                A1[2 * q + 1] = fma2(vb, w.y, A1[2 * q + 1]);
            }
        }
#pragma unroll
        for (int p = 0; p < 16; p++) {
            float u0, u1, v0, v1;
            unpack2(A0[p], u0, u1);
            unpack2(A1[p], v0, v1);
            h1a[c * 32 + 2 * p]     = fmaxf(u0, 0.f);
            h1a[c * 32 + 2 * p + 1] = fmaxf(u1, 0.f);
            h1b[c * 32 + 2 * p]     = fmaxf(v0, 0.f);
            h1b[c * 32 + 2 * p + 1] = fmaxf(v1, 0.f);
        }
    }

    // ---- layer 2 (4 chunks of 16) fused into heads
    u64 HA[16], HB[16];
#pragma unroll
    for (int p = 0; p < 16; p++) { HA[p] = hbu[p]; HB[p] = HA[p]; }

#pragma unroll
    for (int c = 0; c < 4; c++) {
        u64 C0[8], C1[8];
#pragma unroll
        for (int p = 0; p < 8; p++) { C0[p] = b2u[c * 8 + p]; C1[p] = C0[p]; }
#pragma unroll
        for (int i = 0; i < 64; i++) {
            u64 va = pack2(h1a[i], h1a[i]);
            u64 vb = pack2(h1b[i], h1b[i]);
#pragma unroll
            for (int q = 0; q < 4; q++) {
                ulonglong2 w = w2v[i * 16 + c * 4 + q];
                C0[2 * q]     = fma2(va, w.x, C0[2 * q]);
                C0[2 * q + 1] = fma2(va, w.y, C0[2 * q + 1]);
                C1[2 * q]     = fma2(vb, w.x, C1[2 * q]);
                C1[2 * q + 1] = fma2(vb, w.y, C1[2 * q + 1]);
            }
        }
#pragma unroll
        for (int p = 0; p < 8; p++) {
            float r0, r1, s0, s1;
            unpack2(C0[p], r0, r1);
            unpack2(C1[p], s0, s1);
            r0 = fmaxf(r0, 0.f); r1 = fmaxf(r1, 0.f);
            s0 = fmaxf(s0, 0.f); s1 = fmaxf(s1, 0.f);
            int k0 = c * 16 + 2 * p;
            int k1 = k0 + 1;
            u64 va0 = pack2(r0, r0), vb0 = pack2(s0, s0);
            u64 va1 = pack2(r1, r1), vb1 = pack2(s1, s1);
#pragma unroll
            for (int q = 0; q < 4; q++) {
                ulonglong2 w0 = whv[k0 * 4 + q];
                HA[2 * q]     = fma2(va0, w0.x, HA[2 * q]);
                HA[2 * q + 1] = fma2(va0, w0.y, HA[2 * q + 1]);
                HB[2 * q]     = fma2(vb0, w0.x, HB[2 * q]);
                HB[2 * q + 1] = fma2(vb0, w0.y, HB[2 * q + 1]);
                ulonglong2 w1x = whv[k1 * 4 + q];
                HA[2 * q]     = fma2(va1, w1x.x, HA[2 * q]);
                HA[2 * q + 1] = fma2(va1, w1x.y, HA[2 * q + 1]);
                HB[2 * q]     = fma2(vb1, w1x.x, HB[2 * q]);
                HB[2 * q + 1] = fma2(vb1, w1x.y, HB[2 * q + 1]);
            }
        }
    }

    float oa[32], ob[32];
#pragma unroll
    for (int p = 0; p < 16; p++) {
        unpack2(HA[p], oa[2 * p], oa[2 * p + 1]);
        unpack2(HB[p], ob[2 * p], ob[2 * p + 1]);
    }

    {
        float xv = x[ia];
        float amax = oa[20];
#pragma unroll
        for (int k = 1; k < 10; k++) amax = fmaxf(amax, oa[20 + k]);
        float asum = 0.f;
#pragma unroll
        for (int k = 0; k < 10; k++) asum += __expf(oa[20 + k] - amax);
        float lc = amax + __logf(asum);
        float comp[10];
        float cmax = -1e30f;
#pragma unroll
        for (int k = 0; k < 10; k++) {
            float ls = oa[10 + k];
            float z = (xv - oa[k]) * __expf(-ls);
            comp[k] = oa[20 + k] - lc - ls + NEG_HALF_LOG2PI - 0.5f * z * z;
            cmax = fmaxf(cmax, comp[k]);
        }
        float csum = 0.f;
#pragma unroll
        for (int k = 0; k < 10; k++) csum += __expf(comp[k] - cmax);
        g_logp[ia] = cmax + __logf(csum);
    }
    {
        float xv = x[ib];
        float amax = ob[20];
#pragma unroll
        for (int k = 1; k < 10; k++) amax = fmaxf(amax, ob[20 + k]);
        float asum = 0.f;
#pragma unroll
        for (int k = 0; k < 10; k++) asum += __expf(ob[20 + k] - amax);
        float lc = amax + __logf(asum);
        float comp[10];
        float cmax = -1e30f;
#pragma unroll
        for (int k = 0; k < 10; k++) {
            float ls = ob[10 + k];
            float z = (xv - ob[k]) * __expf(-ls);
            comp[k] = ob[20 + k] - lc - ls + NEG_HALF_LOG2PI - 0.5f * z * z;
            cmax = fmaxf(cmax, comp[k]);
        }
        float csum = 0.f;
#pragma unroll
        for (int k = 0; k < 10; k++) csum += __expf(comp[k] - cmax);
        g_logp[ib] = cmax + __logf(csum);
    }
}

// ---------------- reduce: out[n] = exp(sum_t logp[n,t]); warp per n
__global__ void __launch_bounds__(256) red_kernel(float* __restrict__ out)
{
    int wid = threadIdx.x >> 5;
    int L = threadIdx.x & 31;
    int n = blockIdx.x * 8 + wid;
    const float* lp = g_logp + (size_t)n * T;
    float s = lp[L] + lp[L + 32] + lp[L + 64] + lp[L + 96];
#pragma unroll
    for (int o = 16; o > 0; o >>= 1) s += __shfl_xor_sync(FULLMASK, s, o);
    if (L == 0) out[n] = __expf(s);
}

extern "C" void kernel_launch(void* const* d_in, const int* in_sizes, int n_in,
                              void* d_out, int out_size)
{
    (void)in_sizes; (void)n_in; (void)out_size;
    const float* x   = (const float*)d_in[0];
    const float* e1w = (const float*)d_in[1];
    const float* e1b = (const float*)d_in[2];
    const float* e2w = (const float*)d_in[3];
    const float* e2b = (const float*)d_in[4];
    const float* A   = (const float*)d_in[5];
    const float* iw  = (const float*)d_in[6];
    const float* w1  = (const float*)d_in[7];
    const float* b1  = (const float*)d_in[8];
    const float* w2  = (const float*)d_in[9];
    const float* b2  = (const float*)d_in[10];
    const float* muw = (const float*)d_in[11];
    const float* mub = (const float*)d_in[12];
    const float* sgw = (const float*)d_in[13];
    const float* sgb = (const float*)d_in[14];
    const float* alw = (const float*)d_in[15];
    const float* alb = (const float*)d_in[16];
    float* out = (float*)d_out;

    // Fresh stream/events each call (no statics, no frees; kernel_launch is
    // invoked only a handful of times before graph replay takes over).
    cudaStream_t sB;
    cudaStreamCreateWithFlags(&sB, cudaStreamNonBlocking);
    cudaEvent_t evEnc, evP, evR[NCHUNK];
    cudaEventCreateWithFlags(&evEnc, cudaEventDisableTiming);
    cudaEventCreateWithFlags(&evP, cudaEventDisableTiming);
    for (int c = 0; c < NCHUNK; c++)
        cudaEventCreateWithFlags(&evR[c], cudaEventDisableTiming);

    probe_kernel<<<1, 32>>>();
    probe2_kernel<<<1, 32>>>();
    enc_kernel<<<(N_SEQ * T + 255) / 256, 256>>>(x, e1w, e1b, e2w, e2b);
    cudaEventRecord(evEnc, 0);
    cudaStreamWaitEvent(sB, evEnc, 0);

    for (int c = 0; c < NCHUNK; c++) {
        rec_kernel<<<CH_SEQ / 8, 128>>>(A, iw, c * CH_SEQ);
        cudaEventRecord(evR[c], 0);
        cudaStreamWaitEvent(sB, evR[c], 0);
        phi_kernel<<<CH_ITEMS / 2 / 128, 128, 0, sB>>>(
            x, w1, b1, w2, b2, muw, mub, sgw, sgb, alw, alb, c * CH_ITEMS);
    }

    cudaEventRecord(evP, sB);
    cudaStreamWaitEvent(0, evP, 0);
    red_kernel<<<N_SEQ / 8, 256>>>(out);
}

// round 9
// speedup vs baseline: 3.3043x; 3.3043x over previous
#include <cuda_runtime.h>

#define FULLMASK 0xFFFFFFFFu

namespace {
constexpr int N_SEQ = 4096;
constexpr int T = 128;
constexpr int HALF_ITEMS = N_SEQ * T / 2; // 262144
constexpr float NEG_HALF_LOG2PI = -0.91893853320467274f;
}

__device__ float g_enc[(size_t)N_SEQ * T * 8];
__device__ float g_th[(size_t)N_SEQ * T * 32];
__device__ float g_logp[(size_t)N_SEQ * T];
__device__ float g_dummy[32];

typedef unsigned long long u64;

__device__ __forceinline__ u64 pack2(float lo, float hi)
{
    u64 r;
    asm("mov.b64 %0, {%1, %2};" : "=l"(r) : "f"(lo), "f"(hi));
    return r;
}
__device__ __forceinline__ void unpack2(u64 v, float& lo, float& hi)
{
    asm("mov.b64 {%0, %1}, %2;" : "=f"(lo), "=f"(hi) : "l"(v));
}
__device__ __forceinline__ u64 fma2(u64 a, u64 b, u64 c)
{
    u64 d;
    asm("fma.rn.f32x2 %0, %1, %2, %3;" : "=l"(d) : "l"(a), "l"(b), "l"(c));
    return d;
}
__device__ __forceinline__ u64 mul2(u64 a, u64 b)
{
    u64 d;
    asm("mul.rn.f32x2 %0, %1, %2;" : "=l"(d) : "l"(a), "l"(b));
    return d;
}

// ---------------- probes (so ncu's captured launch index 3 == full rec)
__global__ void probe_kernel()
{
    if (threadIdx.x == 0 && blockIdx.x == 0) g_dummy[0] = 1.0f;
}
__global__ void probe2_kernel()
{
    if (threadIdx.x == 0 && blockIdx.x == 0) g_dummy[1] = 1.0f;
}

// ---------------- encoder: g_enc[n][t][d] = tanh(relu(x*w1+b1) @ w2 + b2)
__global__ void enc_kernel(const float* __restrict__ x,
                           const float* __restrict__ e1w, const float* __restrict__ e1b,
                           const float* __restrict__ e2w, const float* __restrict__ e2b)
{
    __shared__ float s1w[64], s1b[64], s2w[64 * 8], s2b[8];
    int tid = threadIdx.x;
    if (tid < 64) { s1w[tid] = e1w[tid]; s1b[tid] = e1b[tid]; }
    if (tid < 8) s2b[tid] = e2b[tid];
    for (int i = tid; i < 64 * 8; i += blockDim.x) s2w[i] = e2w[i];
    __syncthreads();
    int idx = blockIdx.x * blockDim.x + tid;
    if (idx >= N_SEQ * T) return;
    float xv = x[idx];
    float acc[8];
#pragma unroll
    for (int d = 0; d < 8; d++) acc[d] = s2b[d];
#pragma unroll 8
    for (int h = 0; h < 64; h++) {
        float e = fmaxf(fmaf(xv, s1w[h], s1b[h]), 0.f);
#pragma unroll
        for (int d = 0; d < 8; d++) acc[d] = fmaf(e, s2w[h * 8 + d], acc[d]);
    }
    float4 o0 = make_float4(tanhf(acc[0]), tanhf(acc[1]), tanhf(acc[2]), tanhf(acc[3]));
    float4 o1 = make_float4(tanhf(acc[4]), tanhf(acc[5]), tanhf(acc[6]), tanhf(acc[7]));
    float4* op = reinterpret_cast<float4*>(g_enc + (size_t)idx * 8);
    op[0] = o0;
    op[1] = o1;
}

// ---------------- recurrence (R6 design, FULL GRID): 2-warp pair, 4 seqs,
// i-contraction split across the pair, shuffle broadcast, one named 64-thread
// barrier per step, parity double-buffered partials, e prefetched.
// Block = 128 threads = 2 pairs = 8 sequences. Grid = 512.
__global__ void __launch_bounds__(128) rec_kernel(const float* __restrict__ A,
                                                  const float* __restrict__ initw)
{
    __shared__ ulonglong2 A4[2048];      // [(i*2+q)*32 + L]
    __shared__ float part[2][4][4][32];  // [parity][warpInBlock][seq][lane]
    __shared__ float in_s[32];

    int tid = threadIdx.x;
    for (int idx = tid; idx < 2048; idx += 128) {
        int i = idx >> 6, q = (idx >> 5) & 1, L = idx & 31;
        const float* base = A + i * 256 + q * 128 + L;
        ulonglong2 v;
        v.x = pack2(base[0], base[32]);
        v.y = pack2(base[64], base[96]);
        A4[idx] = v;
    }
    if (tid < 32) in_s[tid] = initw[tid];
    __syncthreads();

    int wib = tid >> 5;          // 0..3 warp in block
    int pairIB = wib >> 1;       // 0..1
    int half = wib & 1;          // which i half
    int L = tid & 31;
    int pairG = blockIdx.x * 2 + pairIB;
    int n0 = pairG * 4;
    int barId = 1 + pairIB;

    float tmp[4];
    float init = in_s[L];
#pragma unroll
    for (int s = 0; s < 4; s++) tmp[s] = init;

    {
        float th0 = tanhf(init);
        int s0 = half * 2;
        g_th[((size_t)(n0 + s0) * T) * 32 + L] = th0;
        g_th[((size_t)(n0 + s0 + 1) * T) * 32 + L] = th0;
    }

    const float4* ep[4];
#pragma unroll
    for (int s = 0; s < 4; s++)
        ep[s] = reinterpret_cast<const float4*>(g_enc + (size_t)(n0 + s) * T * 8);

    int iBase = half * 16;

    float4 ec0[4], ec1[4];
#pragma unroll
    for (int s = 0; s < 4; s++) { ec0[s] = ep[s][0]; ec1[s] = ep[s][1]; }

#pragma unroll 1
    for (int t = 1; t < T; t++) {
        int tn = (t < T - 1) ? t : T - 2;
        float4 en0[4], en1[4];
#pragma unroll
        for (int s = 0; s < 4; s++) { en0[s] = ep[s][tn * 2]; en1[s] = ep[s][tn * 2 + 1]; }

        u64 B[4][4];
#pragma unroll
        for (int s = 0; s < 4; s++)
#pragma unroll
            for (int k = 0; k < 4; k++) B[s][k] = 0ull;

#pragma unroll 8
        for (int ii = 0; ii < 16; ii++) {
            int i = iBase + ii;
            ulonglong2 a0 = A4[(i * 2 + 0) * 32 + L];
            ulonglong2 a1 = A4[(i * 2 + 1) * 32 + L];
#pragma unroll
            for (int s = 0; s < 4; s++) {
                float vs = __shfl_sync(FULLMASK, tmp[s], i);
                u64 vv = pack2(vs, vs);
                B[s][0] = fma2(vv, a0.x, B[s][0]);
                B[s][1] = fma2(vv, a0.y, B[s][1]);
                B[s][2] = fma2(vv, a1.x, B[s][2]);
                B[s][3] = fma2(vv, a1.y, B[s][3]);
            }
        }

        int par = t & 1;
#pragma unroll
        for (int s = 0; s < 4; s++) {
            u64 acc = mul2(pack2(ec0[s].x, ec0[s].y), B[s][0]);
            acc = fma2(pack2(ec0[s].z, ec0[s].w), B[s][1], acc);
            acc = fma2(pack2(ec1[s].x, ec1[s].y), B[s][2], acc);
            acc = fma2(pack2(ec1[s].z, ec1[s].w), B[s][3], acc);
            float lo, hi;
            unpack2(acc, lo, hi);
            part[par][wib][s][L] = lo + hi;
        }

        asm volatile("bar.sync %0, 64;" :: "r"(barId) : "memory");

        int partner = wib ^ 1;
#pragma unroll
        for (int s = 0; s < 4; s++)
            tmp[s] = part[par][wib][s][L] + part[par][partner][s][L];

        int s0 = half * 2;
        g_th[((size_t)(n0 + s0) * T + t) * 32 + L] = tanhf(tmp[s0]);
        g_th[((size_t)(n0 + s0 + 1) * T + t) * 32 + L] = tanhf(tmp[s0 + 1]);

#pragma unroll
        for (int s = 0; s < 4; s++) { ec0[s] = en0[s]; ec1[s] = en1[s]; }
    }
}

// ---------------- phi (R7 design, FULL GRID): two items per thread.
__global__ void __launch_bounds__(128) phi_kernel(
    const float* __restrict__ x,
    const float* __restrict__ w1, const float* __restrict__ b1,
    const float* __restrict__ w2, const float* __restrict__ b2,
    const float* __restrict__ muw, const float* __restrict__ mub,
    const float* __restrict__ sgw, const float* __restrict__ sgb,
    const float* __restrict__ alw, const float* __restrict__ alb)
{
    __shared__ float sm[8352];
    int tid = threadIdx.x;

    for (int i = tid; i < 2048; i += 128) sm[i] = w1[i];
    for (int i = tid; i < 4096; i += 128) sm[2048 + i] = w2[i];
    for (int i = tid; i < 2048; i += 128) {
        int k = i >> 5, c = i & 31;
        float v = 0.f;
        if (c < 10) v = muw[k * 10 + c];
        else if (c < 20) v = sgw[k * 10 + (c - 10)];
        else if (c < 30) v = alw[k * 10 + (c - 20)];
        sm[6144 + i] = v;
    }
    if (tid < 64) { sm[8192 + tid] = b1[tid]; sm[8256 + tid] = b2[tid]; }
    if (tid < 32) {
        float v = 0.f;
        if (tid < 10) v = mub[tid];
        else if (tid < 20) v = sgb[tid - 10];
        else if (tid < 30) v = alb[tid - 20];
        sm[8320 + tid] = v;
    }
    __syncthreads();

    const ulonglong2* w1v = reinterpret_cast<const ulonglong2*>(sm);
    const ulonglong2* w2v = reinterpret_cast<const ulonglong2*>(sm + 2048);
    const ulonglong2* whv = reinterpret_cast<const ulonglong2*>(sm + 6144);
    const u64* b1u = reinterpret_cast<const u64*>(sm + 8192);
    const u64* b2u = reinterpret_cast<const u64*>(sm + 8256);
    const u64* hbu = reinterpret_cast<const u64*>(sm + 8320);

    int ia = blockIdx.x * 128 + tid;
    int ib = ia + HALF_ITEMS;
    const float4* tpa = reinterpret_cast<const float4*>(g_th + (size_t)ia * 32);
    const float4* tpb = reinterpret_cast<const float4*>(g_th + (size_t)ib * 32);

    float tha[32], thb[32];
#pragma unroll
    for (int g = 0; g < 8; g++) {
        float4 v = tpa[g];
        tha[4 * g] = v.x; tha[4 * g + 1] = v.y; tha[4 * g + 2] = v.z; tha[4 * g + 3] = v.w;
        float4 u = tpb[g];
        thb[4 * g] = u.x; thb[4 * g + 1] = u.y; thb[4 * g + 2] = u.z; thb[4 * g + 3] = u.w;
    }

    // ---- layer 1: 2 chunks of 32 neurons
    float h1a[64], h1b[64];
#pragma unroll
    for (int c = 0; c < 2; c++) {
        u64 A0[16], A1[16];
#pragma unroll
        for (int p = 0; p < 16; p++) { A0[p] = b1u[c * 16 + p]; A1[p] = A0[p]; }
#pragma unroll
        for (int i = 0; i < 32; i++) {
            u64 va = pack2(tha[i], tha[i]);
            u64 vb = pack2(thb[i], thb[i]);
#pragma unroll
            for (int q = 0; q < 8; q++) {
                ulonglong2 w = w1v[i * 16 + c * 8 + q];
                A0[2 * q]     = fma2(va, w.x, A0[2 * q]);
                A0[2 * q + 1] = fma2(va, w.y, A0[2 * q + 1]);
                A1[2 * q]     = fma2(vb, w.x, A1[2 * q]);
                A1[2 * q + 1] = fma2(vb, w.y, A1[2 * q + 1]);
            }
        }
#pragma unroll
        for (int p = 0; p < 16; p++) {
            float u0, u1, v0, v1;
            unpack2(A0[p], u0, u1);
            unpack2(A1[p], v0, v1);
            h1a[c * 32 + 2 * p]     = fmaxf(u0, 0.f);
            h1a[c * 32 + 2 * p + 1] = fmaxf(u1, 0.f);
            h1b[c * 32 + 2 * p]     = fmaxf(v0, 0.f);
            h1b[c * 32 + 2 * p + 1] = fmaxf(v1, 0.f);
        }
    }

    // ---- layer 2 (4 chunks of 16) fused into heads
    u64 HA[16], HB[16];
#pragma unroll
    for (int p = 0; p < 16; p++) { HA[p] = hbu[p]; HB[p] = HA[p]; }

#pragma unroll
    for (int c = 0; c < 4; c++) {
        u64 C0[8], C1[8];
#pragma unroll
        for (int p = 0; p < 8; p++) { C0[p] = b2u[c * 8 + p]; C1[p] = C0[p]; }
#pragma unroll
        for (int i = 0; i < 64; i++) {
            u64 va = pack2(h1a[i], h1a[i]);
            u64 vb = pack2(h1b[i], h1b[i]);
#pragma unroll
            for (int q = 0; q < 4; q++) {
                ulonglong2 w = w2v[i * 16 + c * 4 + q];
                C0[2 * q]     = fma2(va, w.x, C0[2 * q]);
                C0[2 * q + 1] = fma2(va, w.y, C0[2 * q + 1]);
                C1[2 * q]     = fma2(vb, w.x, C1[2 * q]);
                C1[2 * q + 1] = fma2(vb, w.y, C1[2 * q + 1]);
            }
        }
#pragma unroll
        for (int p = 0; p < 8; p++) {
            float r0, r1, s0, s1;
            unpack2(C0[p], r0, r1);
            unpack2(C1[p], s0, s1);
            r0 = fmaxf(r0, 0.f); r1 = fmaxf(r1, 0.f);
            s0 = fmaxf(s0, 0.f); s1 = fmaxf(s1, 0.f);
            int k0 = c * 16 + 2 * p;
            int k1 = k0 + 1;
            u64 va0 = pack2(r0, r0), vb0 = pack2(s0, s0);
            u64 va1 = pack2(r1, r1), vb1 = pack2(s1, s1);
#pragma unroll
            for (int q = 0; q < 4; q++) {
                ulonglong2 w0 = whv[k0 * 4 + q];
                HA[2 * q]     = fma2(va0, w0.x, HA[2 * q]);
                HA[2 * q + 1] = fma2(va0, w0.y, HA[2 * q + 1]);
                HB[2 * q]     = fma2(vb0, w0.x, HB[2 * q]);
                HB[2 * q + 1] = fma2(vb0, w0.y, HB[2 * q + 1]);
                ulonglong2 w1x = whv[k1 * 4 + q];
                HA[2 * q]     = fma2(va1, w1x.x, HA[2 * q]);
                HA[2 * q + 1] = fma2(va1, w1x.y, HA[2 * q + 1]);
                HB[2 * q]     = fma2(vb1, w1x.x, HB[2 * q]);
                HB[2 * q + 1] = fma2(vb1, w1x.y, HB[2 * q + 1]);
            }
        }
    }

    float oa[32], ob[32];
#pragma unroll
    for (int p = 0; p < 16; p++) {
        unpack2(HA[p], oa[2 * p], oa[2 * p + 1]);
        unpack2(HB[p], ob[2 * p], ob[2 * p + 1]);
    }

    {
        float xv = x[ia];
        float amax = oa[20];
#pragma unroll
        for (int k = 1; k < 10; k++) amax = fmaxf(amax, oa[20 + k]);
        float asum = 0.f;
#pragma unroll
        for (int k = 0; k < 10; k++) asum += __expf(oa[20 + k] - amax);
        float lc = amax + __logf(asum);
        float comp[10];
        float cmax = -1e30f;
#pragma unroll
        for (int k = 0; k < 10; k++) {
            float ls = oa[10 + k];
            float z = (xv - oa[k]) * __expf(-ls);
            comp[k] = oa[20 + k] - lc - ls + NEG_HALF_LOG2PI - 0.5f * z * z;
            cmax = fmaxf(cmax, comp[k]);
        }
        float csum = 0.f;
#pragma unroll
        for (int k = 0; k < 10; k++) csum += __expf(comp[k] - cmax);
        g_logp[ia] = cmax + __logf(csum);
    }
    {
        float xv = x[ib];
        float amax = ob[20];
#pragma unroll
        for (int k = 1; k < 10; k++) amax = fmaxf(amax, ob[20 + k]);
        float asum = 0.f;
#pragma unroll
        for (int k = 0; k < 10; k++) asum += __expf(ob[20 + k] - amax);
        float lc = amax + __logf(asum);
        float comp[10];
        float cmax = -1e30f;
#pragma unroll
        for (int k = 0; k < 10; k++) {
            float ls = ob[10 + k];
            float z = (xv - ob[k]) * __expf(-ls);
            comp[k] = ob[20 + k] - lc - ls + NEG_HALF_LOG2PI - 0.5f * z * z;
            cmax = fmaxf(cmax, comp[k]);
        }
        float csum = 0.f;
#pragma unroll
        for (int k = 0; k < 10; k++) csum += __expf(comp[k] - cmax);
        g_logp[ib] = cmax + __logf(csum);
    }
}

// ---------------- reduce: out[n] = exp(sum_t logp[n,t]); warp per n
__global__ void __launch_bounds__(256) red_kernel(float* __restrict__ out)
{
    int wid = threadIdx.x >> 5;
    int L = threadIdx.x & 31;
    int n = blockIdx.x * 8 + wid;
    const float* lp = g_logp + (size_t)n * T;
    float s = lp[L] + lp[L + 32] + lp[L + 64] + lp[L + 96];
#pragma unroll
    for (int o = 16; o > 0; o >>= 1) s += __shfl_xor_sync(FULLMASK, s, o);
    if (L == 0) out[n] = __expf(s);
}

extern "C" void kernel_launch(void* const* d_in, const int* in_sizes, int n_in,
                              void* d_out, int out_size)
{
    (void)in_sizes; (void)n_in; (void)out_size;
    const float* x   = (const float*)d_in[0];
    const float* e1w = (const float*)d_in[1];
    const float* e1b = (const float*)d_in[2];
    const float* e2w = (const float*)d_in[3];
    const float* e2b = (const float*)d_in[4];
    const float* A   = (const float*)d_in[5];
    const float* iw  = (const float*)d_in[6];
    const float* w1  = (const float*)d_in[7];
    const float* b1  = (const float*)d_in[8];
    const float* w2  = (const float*)d_in[9];
    const float* b2  = (const float*)d_in[10];
    const float* muw = (const float*)d_in[11];
    const float* mub = (const float*)d_in[12];
    const float* sgw = (const float*)d_in[13];
    const float* sgb = (const float*)d_in[14];
    const float* alw = (const float*)d_in[15];
    const float* alb = (const float*)d_in[16];
    float* out = (float*)d_out;

    probe_kernel<<<1, 32>>>();
    probe2_kernel<<<1, 32>>>();
    enc_kernel<<<(N_SEQ * T + 255) / 256, 256>>>(x, e1w, e1b, e2w, e2b);
    rec_kernel<<<512, 128>>>(A, iw);
    phi_kernel<<<HALF_ITEMS / 128, 128>>>(
        x, w1, b1, w2, b2, muw, mub, sgw, sgb, alw, alb);
    red_kernel<<<N_SEQ / 8, 256>>>(out);
}